// round 14
// baseline (speedup 1.0000x reference)
#include <cuda_runtime.h>
#include <math.h>

// DSA_43722767073506 — algebraically collapsed, fused kernel (FINAL, == v8).
//
// Math (derived from the reference):
//  * log_softmax over a size-1 axis == 0 exactly => beta == 0 => ctx == 0 at
//    every scan step. Only the FINAL decoder step (driven by d[:, T-2])
//    reaches the output; x / encoder / attention params are dead.
//  * f-gate dead (c0 = 0); feat = [h, 0] so only d1_w[:, :H] matters.
//  * out_b = weff . h_b + beff,  weff = d2_w @ d1_w[:, :H],
//    beff = d2_w . d1_b + d2_b  (folded into the per-warp reduction).
//
// Convergence evidence (rounds 4-13): this exact source measured
// 6.624 / 6.880 / 6.880 / 8.960 / 6.656 / 6.656 us across six runs with
// bit-identical rel_err — spread is container clock state, not kernel
// content. Three distinct bodies previously tied at 6.624us; every shape
// variant regressed. ~6.6us graph-replay floor; all pipes <0.3%.
// Measured-best configuration, submitted as final.

#define HID 128

__device__ __forceinline__ float tanh_fast(float x) {
    float y;
    asm("tanh.approx.f32 %0, %1;" : "=f"(y) : "f"(x));
    return y;
}

__global__ void __launch_bounds__(1024)
dsa_fused_kernel(const float* __restrict__ d,     // (B, T-1)
                 const float* __restrict__ Wd,    // (4H,)
                 const float* __restrict__ bd,    // (4H,)
                 const float* __restrict__ decw,  // (H+1,) -> [0]
                 const float* __restrict__ decb,  // (1,)
                 const float* __restrict__ d1w,   // (H, 2H) row-major
                 const float* __restrict__ d1b,   // (H,)
                 const float* __restrict__ d2w,   // (H,)
                 const float* __restrict__ d2b,   // (1,)
                 float* __restrict__ out,         // (B,)
                 int Bn, int Tm1)
{
    __shared__ float sm[32 * HID];   // GEMV partials, [warp][col]
    __shared__ float sweff[HID];

    const int t    = threadIdx.x;
    const int lane = t & 31;
    const int w    = t >> 5;

    // ================= prefetch wave: issue EVERY gmem load now =================
    // GEMV operands: warp w owns rows 4w..4w+3, lane owns cols 4l..4l+3
    float  ga[4];
    float4 gv[4];
#pragma unroll
    for (int r = 0; r < 4; ++r) {
        const int j = w * 4 + r;
        ga[r] = d2w[j];
        gv[r] = ((const float4*)(d1w + (size_t)j * (2 * HID)))[lane];
    }

    // epilogue scalars (one batch per warp, B == 32)
    float dval = 0.0f;
    if (w < Bn) dval = d[w * Tm1 + (Tm1 - 1)];
    const float dw0  = decw[0];
    const float db0  = decb[0];
    const float d2bv = d2b[0];

    float wi[4], wg[4], wo[4], bi[4], bg[4], bo[4], a2[4], b1[4];
#pragma unroll
    for (int m = 0; m < 4; ++m) {
        const int k = lane + 32 * m;
        wi[m] = Wd[k];
        wg[m] = Wd[2 * HID + k];
        wo[m] = Wd[3 * HID + k];
        bi[m] = bd[k];
        bg[m] = bd[2 * HID + k];
        bo[m] = bd[3 * HID + k];
        a2[m] = d2w[k];
        b1[m] = d1b[k];
    }

    // ============== compute h + beff-partials (overlaps GEMV loads) ==============
    const float u = fmaf(dval, dw0, db0);   // decoder input at final step
    float h4[4];
    float rb = 0.0f;                         // beff partial: sum_k d2w[k]*d1b[k]
#pragma unroll
    for (int m = 0; m < 4; ++m) {
        const float zi = fmaf(u, wi[m], bi[m]);
        const float zg = fmaf(u, wg[m], bg[m]);
        const float zo = fmaf(u, wo[m], bo[m]);
        // sigmoid(x) = 0.5*tanh(x/2) + 0.5 — HW MUFU.TANH
        const float si = fmaf(0.5f, tanh_fast(0.5f * zi), 0.5f);
        const float so = fmaf(0.5f, tanh_fast(0.5f * zo), 0.5f);
        const float c  = si * tanh_fast(zg);
        h4[m] = so * tanh_fast(c);
        rb = fmaf(a2[m], b1[m], rb);
    }

    // ======================= GEMV partials -> shared =======================
    float4 acc;
    acc.x = ga[0] * gv[0].x; acc.y = ga[0] * gv[0].y;
    acc.z = ga[0] * gv[0].z; acc.w = ga[0] * gv[0].w;
#pragma unroll
    for (int r = 1; r < 4; ++r) {
        acc.x = fmaf(ga[r], gv[r].x, acc.x);
        acc.y = fmaf(ga[r], gv[r].y, acc.y);
        acc.z = fmaf(ga[r], gv[r].z, acc.z);
        acc.w = fmaf(ga[r], gv[r].w, acc.w);
    }
    ((float4*)(sm + w * HID))[lane] = acc;
    __syncthreads();

    // ========== reduce 32 partials per column (t < 128), 4-way tree ==========
    if (t < HID) {
        float s0 = 0.f, s1 = 0.f, s2 = 0.f, s3 = 0.f;
#pragma unroll
        for (int ww = 0; ww < 32; ww += 4) {
            s0 += sm[(ww + 0) * HID + t];
            s1 += sm[(ww + 1) * HID + t];
            s2 += sm[(ww + 2) * HID + t];
            s3 += sm[(ww + 3) * HID + t];
        }
        sweff[t] = (s0 + s1) + (s2 + s3);
    }
    __syncthreads();

    // ======================= final dot + output =======================
    if (w >= Bn) return;

    float r = rb;                        // carries the beff partial
#pragma unroll
    for (int m = 0; m < 4; ++m)
        r = fmaf(sweff[lane + 32 * m], h4[m], r);
#pragma unroll
    for (int off = 16; off; off >>= 1)
        r += __shfl_xor_sync(0xFFFFFFFFu, r, off);

    if (lane == 0)
        out[w] = r + d2bv;
}

extern "C" void kernel_launch(void* const* d_in, const int* in_sizes, int n_in,
                              void* d_out, int out_size)
{
    // metadata order: x, d, W_ih_e, b_e, W_ih_d, b_d, att_w1, att_b1, att_w2,
    //                 att_b2, att_v, att_vb, dec_w, dec_b, d1_w, d1_b, d2_w, d2_b
    const float* d    = (const float*)d_in[1];
    const float* Wd   = (const float*)d_in[4];
    const float* bd   = (const float*)d_in[5];
    const float* decw = (const float*)d_in[12];
    const float* decb = (const float*)d_in[13];
    const float* d1w  = (const float*)d_in[14];
    const float* d1b  = (const float*)d_in[15];
    const float* d2w  = (const float*)d_in[16];
    const float* d2b  = (const float*)d_in[17];

    const int Bn  = out_size;                 // 32
    const int Tm1 = in_sizes[1] / Bn;         // 99

    dsa_fused_kernel<<<1, 1024>>>(d, Wd, bd, decw, decb,
                                  d1w, d1b, d2w, d2b,
                                  (float*)d_out, Bn, Tm1);
}

// round 15
// speedup vs baseline: 1.0097x; 1.0097x over previous
#include <cuda_runtime.h>
#include <math.h>

// DSA_43722767073506 — algebraically collapsed, fused kernel (FINAL, == v8).
//
// Math (derived from the reference):
//  * log_softmax over a size-1 axis == 0 exactly => beta == 0 => ctx == 0 at
//    every scan step. Only the FINAL decoder step (driven by d[:, T-2])
//    reaches the output; x / encoder / attention params are dead.
//  * f-gate dead (c0 = 0); feat = [h, 0] so only d1_w[:, :H] matters.
//  * out_b = weff . h_b + beff,  weff = d2_w @ d1_w[:, :H],
//    beff = d2_w . d1_b + d2_b  (folded into the per-warp reduction).
//
// Convergence evidence (rounds 4-14): this exact source measured
// 6.624 / 6.880 / 6.880 / 8.960 / 6.656 / 6.656 / 6.688 us across seven runs
// with bit-identical rel_err — spread is container clock state, not kernel
// content. Three distinct bodies previously tied at 6.624us; every shape
// variant regressed. ~6.6us graph-replay floor; all pipes <0.3%.
// Measured-best configuration, submitted as final.

#define HID 128

__device__ __forceinline__ float tanh_fast(float x) {
    float y;
    asm("tanh.approx.f32 %0, %1;" : "=f"(y) : "f"(x));
    return y;
}

__global__ void __launch_bounds__(1024)
dsa_fused_kernel(const float* __restrict__ d,     // (B, T-1)
                 const float* __restrict__ Wd,    // (4H,)
                 const float* __restrict__ bd,    // (4H,)
                 const float* __restrict__ decw,  // (H+1,) -> [0]
                 const float* __restrict__ decb,  // (1,)
                 const float* __restrict__ d1w,   // (H, 2H) row-major
                 const float* __restrict__ d1b,   // (H,)
                 const float* __restrict__ d2w,   // (H,)
                 const float* __restrict__ d2b,   // (1,)
                 float* __restrict__ out,         // (B,)
                 int Bn, int Tm1)
{
    __shared__ float sm[32 * HID];   // GEMV partials, [warp][col]
    __shared__ float sweff[HID];

    const int t    = threadIdx.x;
    const int lane = t & 31;
    const int w    = t >> 5;

    // ================= prefetch wave: issue EVERY gmem load now =================
    // GEMV operands: warp w owns rows 4w..4w+3, lane owns cols 4l..4l+3
    float  ga[4];
    float4 gv[4];
#pragma unroll
    for (int r = 0; r < 4; ++r) {
        const int j = w * 4 + r;
        ga[r] = d2w[j];
        gv[r] = ((const float4*)(d1w + (size_t)j * (2 * HID)))[lane];
    }

    // epilogue scalars (one batch per warp, B == 32)
    float dval = 0.0f;
    if (w < Bn) dval = d[w * Tm1 + (Tm1 - 1)];
    const float dw0  = decw[0];
    const float db0  = decb[0];
    const float d2bv = d2b[0];

    float wi[4], wg[4], wo[4], bi[4], bg[4], bo[4], a2[4], b1[4];
#pragma unroll
    for (int m = 0; m < 4; ++m) {
        const int k = lane + 32 * m;
        wi[m] = Wd[k];
        wg[m] = Wd[2 * HID + k];
        wo[m] = Wd[3 * HID + k];
        bi[m] = bd[k];
        bg[m] = bd[2 * HID + k];
        bo[m] = bd[3 * HID + k];
        a2[m] = d2w[k];
        b1[m] = d1b[k];
    }

    // ============== compute h + beff-partials (overlaps GEMV loads) ==============
    const float u = fmaf(dval, dw0, db0);   // decoder input at final step
    float h4[4];
    float rb = 0.0f;                         // beff partial: sum_k d2w[k]*d1b[k]
#pragma unroll
    for (int m = 0; m < 4; ++m) {
        const float zi = fmaf(u, wi[m], bi[m]);
        const float zg = fmaf(u, wg[m], bg[m]);
        const float zo = fmaf(u, wo[m], bo[m]);
        // sigmoid(x) = 0.5*tanh(x/2) + 0.5 — HW MUFU.TANH
        const float si = fmaf(0.5f, tanh_fast(0.5f * zi), 0.5f);
        const float so = fmaf(0.5f, tanh_fast(0.5f * zo), 0.5f);
        const float c  = si * tanh_fast(zg);
        h4[m] = so * tanh_fast(c);
        rb = fmaf(a2[m], b1[m], rb);
    }

    // ======================= GEMV partials -> shared =======================
    float4 acc;
    acc.x = ga[0] * gv[0].x; acc.y = ga[0] * gv[0].y;
    acc.z = ga[0] * gv[0].z; acc.w = ga[0] * gv[0].w;
#pragma unroll
    for (int r = 1; r < 4; ++r) {
        acc.x = fmaf(ga[r], gv[r].x, acc.x);
        acc.y = fmaf(ga[r], gv[r].y, acc.y);
        acc.z = fmaf(ga[r], gv[r].z, acc.z);
        acc.w = fmaf(ga[r], gv[r].w, acc.w);
    }
    ((float4*)(sm + w * HID))[lane] = acc;
    __syncthreads();

    // ========== reduce 32 partials per column (t < 128), 4-way tree ==========
    if (t < HID) {
        float s0 = 0.f, s1 = 0.f, s2 = 0.f, s3 = 0.f;
#pragma unroll
        for (int ww = 0; ww < 32; ww += 4) {
            s0 += sm[(ww + 0) * HID + t];
            s1 += sm[(ww + 1) * HID + t];
            s2 += sm[(ww + 2) * HID + t];
            s3 += sm[(ww + 3) * HID + t];
        }
        sweff[t] = (s0 + s1) + (s2 + s3);
    }
    __syncthreads();

    // ======================= final dot + output =======================
    if (w >= Bn) return;

    float r = rb;                        // carries the beff partial
#pragma unroll
    for (int m = 0; m < 4; ++m)
        r = fmaf(sweff[lane + 32 * m], h4[m], r);
#pragma unroll
    for (int off = 16; off; off >>= 1)
        r += __shfl_xor_sync(0xFFFFFFFFu, r, off);

    if (lane == 0)
        out[w] = r + d2bv;
}

extern "C" void kernel_launch(void* const* d_in, const int* in_sizes, int n_in,
                              void* d_out, int out_size)
{
    // metadata order: x, d, W_ih_e, b_e, W_ih_d, b_d, att_w1, att_b1, att_w2,
    //                 att_b2, att_v, att_vb, dec_w, dec_b, d1_w, d1_b, d2_w, d2_b
    const float* d    = (const float*)d_in[1];
    const float* Wd   = (const float*)d_in[4];
    const float* bd   = (const float*)d_in[5];
    const float* decw = (const float*)d_in[12];
    const float* decb = (const float*)d_in[13];
    const float* d1w  = (const float*)d_in[14];
    const float* d1b  = (const float*)d_in[15];
    const float* d2w  = (const float*)d_in[16];
    const float* d2b  = (const float*)d_in[17];

    const int Bn  = out_size;                 // 32
    const int Tm1 = in_sizes[1] / Bn;         // 99

    dsa_fused_kernel<<<1, 1024>>>(d, Wd, bd, decw, decb,
                                  d1w, d1b, d2w, d2b,
                                  (float*)d_out, Bn, Tm1);
}